// round 1
// baseline (speedup 1.0000x reference)
#include <cuda_runtime.h>
#include <math.h>
#include <stdint.h>

// Problem constants
#define PP   256          // players
#define TT   65536        // time steps
#define UU   128          // units
#define TC   128          // t-steps per scan chunk
#define NC   (TT/TC)      // 512 chunks
#define PTILE 128         // players per GEMM block tile
#define TS   32           // t sub-tile inside GEMM block

// Scratch (device globals: no allocation allowed)
__device__ __align__(16) float g_L[PP*NC];
__device__ __align__(16) float g_H[PP*NC];
__device__ __align__(16) float g_sin[PP*NC];
__device__ __align__(16) float g_y[PP*UU];

// ---- f32x2 packed math (Blackwell) ----
#define FMA_F32X2(d, a, b, c) \
    asm("fma.rn.f32x2 %0, %1, %2, %3;" : "=l"(d) : "l"(a), "l"(b), "l"(c))
#define PACK_F32X2(out, lo, hi) \
    asm("mov.b64 %0, {%1, %2};" : "=l"(out) : "r"(__float_as_uint(lo)), "r"(__float_as_uint(hi)))
#define UNPACK_F32X2(lo, hi, in) \
    asm("mov.b64 {%0, %1}, %2;" : "=r"(lo), "=r"(hi) : "l"(in))

// clamp-monoid combine: left segment (l,h) followed by right segment (l2,h2)
__device__ __forceinline__ void combine(float& l, float& h, float l2, float h2) {
    l = fminf(fmaxf(l, l2), h2);
    h = fminf(fmaxf(h, l2), h2);
}

// ============================================================
// Kernel 1: per-(player, chunk) clamp composition (L, H).
// One warp per chunk of TC=128 elements: 4 elems/lane + warp reduce.
// ============================================================
__global__ void k_chunkred(const float* __restrict__ x, const float* __restrict__ w) {
    int wid  = (blockIdx.x * blockDim.x + threadIdx.x) >> 5;  // 0 .. PP*NC-1
    int lane = threadIdx.x & 31;
    int p = wid >> 9;         // / NC (512)
    int c = wid & (NC - 1);

    float wp = __ldg(&w[p]);
    const float4 xv = *(const float4*)(x + (size_t)p * TT + (size_t)c * TC + lane * 4);
    float x0 = xv.x * wp, x1 = xv.y * wp, x2 = xv.z * wp, x3 = xv.w * wp;

    float l = x0, h = x0 + 1.0f;
    combine(l, h, x1, x1 + 1.0f);
    combine(l, h, x2, x2 + 1.0f);
    combine(l, h, x3, x3 + 1.0f);

    // ordered warp reduction (self = earlier t, shfl_down source = later t)
    #pragma unroll
    for (int d = 1; d < 32; d <<= 1) {
        float lo = __shfl_down_sync(0xffffffffu, l, d);
        float ho = __shfl_down_sync(0xffffffffu, h, d);
        if (lane + d < 32) combine(l, h, lo, ho);
    }
    if (lane == 0) {
        g_L[p * NC + c] = l;
        g_H[p * NC + c] = h;
    }
}

// ============================================================
// Kernel 2: per-player scan over 512 chunk-ops. One warp per player:
// each lane composes 16 chunks, warp-scan of composed ops, replay.
// Also zero-initializes g_y.
// ============================================================
__global__ void k_scan(const float* __restrict__ state) {
    int gtid = blockIdx.x * blockDim.x + threadIdx.x;   // 0..8191
    // zero accumulator buffer (8192 threads * float4 = 32768 floats)
    ((float4*)g_y)[gtid] = make_float4(0.f, 0.f, 0.f, 0.f);

    int p    = gtid >> 5;
    int lane = gtid & 31;
    const int CPL = NC / 32;   // 16 chunks per lane

    float L[CPL], H[CPL];
    int base = p * NC + lane * CPL;
    #pragma unroll
    for (int i = 0; i < CPL; i++) { L[i] = g_L[base + i]; H[i] = g_H[base + i]; }

    // lane-local composition (in t order)
    float l = L[0], h = H[0];
    #pragma unroll
    for (int i = 1; i < CPL; i++) combine(l, h, L[i], H[i]);

    // inclusive warp scan (earlier lanes are the left operand)
    #pragma unroll
    for (int d = 1; d < 32; d <<= 1) {
        float lo = __shfl_up_sync(0xffffffffu, l, d);
        float ho = __shfl_up_sync(0xffffffffu, h, d);
        if (lane >= d) {
            float nl = fminf(fmaxf(lo, l), h);
            float nh = fminf(fmaxf(ho, l), h);
            l = nl; h = nh;
        }
    }
    // exclusive prefix for this lane
    float exl = __shfl_up_sync(0xffffffffu, l, 1);
    float exh = __shfl_up_sync(0xffffffffu, h, 1);

    float s = state[p];
    if (lane > 0) s = fminf(fmaxf(s, exl), exh);

    // replay this lane's 16 chunks, emitting the incoming state per chunk
    #pragma unroll
    for (int i = 0; i < CPL; i++) {
        g_sin[base + i] = s;
        s = fminf(fmaxf(s, L[i]), H[i]);
    }
}

// ============================================================
// Kernel 3: fused replay + GEMM partial.
// Grid: (NC chunks, 2 player-tiles). Block: 256 threads.
// For each 32-t sub-tile: load X transposed, scan in place (threads 0-127)
// while threads 128-255 load the K tile, then 128x128 outer-product GEMM
// with packed f32x2 FMAs (8x8 per thread). AtomicAdd partials at the end.
// ============================================================
__global__ void __launch_bounds__(256, 2)
k_gemm(const float* __restrict__ x, const float* __restrict__ w,
       const float* __restrict__ kern) {
    __shared__ float XS[TS][136];   // x -> s in place; stride 136 (16B-aligned rows, low conflict)
    __shared__ float KT[TS][UU];

    int c  = blockIdx.x;
    int p0 = blockIdx.y * PTILE;
    int tid = threadIdx.x;
    int tx = tid & 15;        // unit-block index  (8 units)
    int ty = tid >> 4;        // player-block index (8 players)

    unsigned long long acc[32];
    #pragma unroll
    for (int i = 0; i < 32; i++) acc[i] = 0ull;   // (+0.f, +0.f)

    float sreg = 0.f, wp = 0.f;
    if (tid < PTILE) {
        sreg = g_sin[(size_t)(p0 + tid) * NC + c];
        wp   = w[p0 + tid];
    }

    const int t0 = c * TC;

    for (int ts = 0; ts < TC; ts += TS) {
        // ---- load X sub-tile transposed: XS[j][p] ----
        {
            int r = tid >> 1, half = tid & 1;
            const float* gp = x + (size_t)(p0 + r) * TT + t0 + ts + half * 16;
            #pragma unroll
            for (int q = 0; q < 4; q++) {
                float4 v = *(const float4*)(gp + q * 4);
                int j = half * 16 + q * 4;
                XS[j + 0][r] = v.x; XS[j + 1][r] = v.y;
                XS[j + 2][r] = v.z; XS[j + 3][r] = v.w;
            }
        }
        __syncthreads();

        if (tid < PTILE) {
            // ---- replay scan for 32 steps, write s in place ----
            float s = sreg;
            #pragma unroll
            for (int j = 0; j < TS; j++) {
                float xv = XS[j][tid] * wp;
                s = fminf(fmaxf(s, xv), xv + 1.0f);
                XS[j][tid] = s;
            }
            sreg = s;
        } else {
            // ---- load K tile: KT[j][u] ----
            int tl = tid - PTILE;           // 0..127
            int j0 = tl >> 2;               // 0..31
            int useg = (tl & 3) * 32;
            const float* gp = kern + (size_t)(t0 + ts + j0) * UU + useg;
            #pragma unroll
            for (int q = 0; q < 8; q++) {
                *(float4*)&KT[j0][useg + q * 4] = *(const float4*)(gp + q * 4);
            }
        }
        __syncthreads();

        // ---- 128x128 outer-product accumulation over 32 t ----
        #pragma unroll 4
        for (int j = 0; j < TS; j++) {
            float4 sa = *(const float4*)&XS[j][ty * 8];
            float4 sb = *(const float4*)&XS[j][ty * 8 + 4];
            const unsigned long long* kp = (const unsigned long long*)&KT[j][tx * 8];
            unsigned long long k0 = kp[0], k1 = kp[1], k2 = kp[2], k3 = kp[3];

            float sv[8] = {sa.x, sa.y, sa.z, sa.w, sb.x, sb.y, sb.z, sb.w};
            #pragma unroll
            for (int i = 0; i < 8; i++) {
                unsigned long long sp;
                PACK_F32X2(sp, sv[i], sv[i]);
                FMA_F32X2(acc[i * 4 + 0], sp, k0, acc[i * 4 + 0]);
                FMA_F32X2(acc[i * 4 + 1], sp, k1, acc[i * 4 + 1]);
                FMA_F32X2(acc[i * 4 + 2], sp, k2, acc[i * 4 + 2]);
                FMA_F32X2(acc[i * 4 + 3], sp, k3, acc[i * 4 + 3]);
            }
        }
        __syncthreads();
    }

    // ---- write partials ----
    #pragma unroll
    for (int i = 0; i < 8; i++) {
        int pr = p0 + ty * 8 + i;
        #pragma unroll
        for (int m = 0; m < 4; m++) {
            unsigned int u0, u1;
            UNPACK_F32X2(u0, u1, acc[i * 4 + m]);
            int uc = tx * 8 + m * 2;
            atomicAdd(&g_y[pr * UU + uc],     __uint_as_float(u0));
            atomicAdd(&g_y[pr * UU + uc + 1], __uint_as_float(u1));
        }
    }
}

// ============================================================
// Kernel 4: epilogue  out = tanh(y + bias)
// ============================================================
__global__ void k_out(const float* __restrict__ bias, float* __restrict__ out) {
    int i = blockIdx.x * blockDim.x + threadIdx.x;   // 0..32767
    out[i] = tanhf(g_y[i] + bias[i & (UU - 1)]);
}

// ============================================================
extern "C" void kernel_launch(void* const* d_in, const int* in_sizes, int n_in,
                              void* d_out, int out_size) {
    const float* inputs = (const float*)d_in[0];   // [P, T]
    const float* pw     = (const float*)d_in[1];   // [P]
    const float* kern   = (const float*)d_in[2];   // [T, U]
    const float* bias   = (const float*)d_in[3];   // [U]
    const float* state  = (const float*)d_in[4];   // [P]
    float* out = (float*)d_out;                    // [P, U]

    // Phase 1: chunk reductions. PP*NC warps = 131072 warps / 8 per block.
    k_chunkred<<<(PP * NC) / 8, 256>>>(inputs, pw);
    // Phase 2: per-player chunk scan (+ zero g_y). 256 warps.
    k_scan<<<32, 256>>>(state);
    // Phase 3: fused replay + GEMM partials.
    k_gemm<<<dim3(NC, PP / PTILE), 256>>>(inputs, pw, kern);
    // Phase 4: epilogue.
    k_out<<<(PP * UU) / 256, 256>>>(bias, out);
}

// round 3
// speedup vs baseline: 1.5585x; 1.5585x over previous
#include <cuda_runtime.h>
#include <cuda_bf16.h>
#include <math.h>
#include <stdint.h>

#define PP 256
#define TT 65536
#define UU 128
#define TC 128
#define NC 512

// ---------------- device scratch ----------------
__device__ __align__(16) float g_L[PP*NC];
__device__ __align__(16) float g_H[PP*NC];
__device__ __align__(16) float g_sin[PP*NC];
__device__ __align__(16) float g_y[PP*UU];
__device__ __align__(16) __nv_bfloat16 g_khi[(size_t)UU*TT];   // [U][T]
__device__ __align__(16) __nv_bfloat16 g_klo[(size_t)UU*TT];   // [U][T]

// ---------------- helpers ----------------
__device__ __forceinline__ uint32_t smem_u32(const void* p) {
    uint32_t a;
    asm("{ .reg .u64 t; cvta.to.shared.u64 t, %1; cvt.u32.u64 %0, t; }" : "=r"(a) : "l"(p));
    return a;
}
__device__ __forceinline__ void cp16(uint32_t dst, const void* src) {
    asm volatile("cp.async.cg.shared.global [%0], [%1], 16;" :: "r"(dst), "l"(src));
}
#define CP_COMMIT() asm volatile("cp.async.commit_group;" ::: "memory")
#define CP_WAIT0()  asm volatile("cp.async.wait_group 0;" ::: "memory")

#define LDSM_X4(d, addr) \
    asm volatile("ldmatrix.sync.aligned.m8n8.x4.shared.b16 {%0,%1,%2,%3}, [%4];" \
        : "=r"((d)[0]), "=r"((d)[1]), "=r"((d)[2]), "=r"((d)[3]) : "r"(addr))

#define MMA_BF16(c, a, b0, b1) \
    asm volatile("mma.sync.aligned.m16n8k16.row.col.f32.bf16.bf16.f32 " \
        "{%0,%1,%2,%3}, {%4,%5,%6,%7}, {%8,%9}, {%0,%1,%2,%3};" \
        : "+f"((c)[0]), "+f"((c)[1]), "+f"((c)[2]), "+f"((c)[3]) \
        : "r"((a)[0]), "r"((a)[1]), "r"((a)[2]), "r"((a)[3]), "r"(b0), "r"(b1))

__device__ __forceinline__ void combine(float& l, float& h, float l2, float h2) {
    l = fminf(fmaxf(l, l2), h2);
    h = fminf(fmaxf(h, l2), h2);
}

// ============================================================
// Phase 1 (fused): chunk reductions + kernel transpose/split
// ============================================================
__global__ void k_phase1(const float* __restrict__ x, const float* __restrict__ w,
                         const float* __restrict__ kern) {
    if (blockIdx.x < (PP * NC) / 8) {
        int wid  = (blockIdx.x * blockDim.x + threadIdx.x) >> 5;
        int lane = threadIdx.x & 31;
        int p = wid >> 9;
        int c = wid & (NC - 1);

        float wp = __ldg(&w[p]);
        const float4 xv = *(const float4*)(x + (size_t)p * TT + (size_t)c * TC + lane * 4);
        float x0 = xv.x * wp, x1 = xv.y * wp, x2 = xv.z * wp, x3 = xv.w * wp;

        float l = x0, h = x0 + 1.0f;
        combine(l, h, x1, x1 + 1.0f);
        combine(l, h, x2, x2 + 1.0f);
        combine(l, h, x3, x3 + 1.0f);
        #pragma unroll
        for (int d = 1; d < 32; d <<= 1) {
            float lo = __shfl_down_sync(0xffffffffu, l, d);
            float ho = __shfl_down_sync(0xffffffffu, h, d);
            if (lane + d < 32) combine(l, h, lo, ho);
        }
        if (lane == 0) { g_L[p * NC + c] = l; g_H[p * NC + c] = h; }
    } else {
        __shared__ __nv_bfloat16 sh[128][72];
        __shared__ __nv_bfloat16 sl[128][72];
        int tb = blockIdx.x - (PP * NC) / 8;
        int t0 = tb * 64;
        int u = threadIdx.x & 127, rh = threadIdx.x >> 7;
        #pragma unroll 8
        for (int rr = 0; rr < 64; rr += 2) {
            int t = t0 + rr + rh;
            float v = __ldg(&kern[(size_t)t * UU + u]);
            __nv_bfloat16 hi = __float2bfloat16(v);
            float lo = v - __bfloat162float(hi);
            sh[u][rr + rh] = hi;
            sl[u][rr + rh] = __float2bfloat16(lo);
        }
        __syncthreads();
        int uu = threadIdx.x >> 1, half = threadIdx.x & 1;
        const uint4* srcH = (const uint4*)&sh[uu][half * 32];
        const uint4* srcL = (const uint4*)&sl[uu][half * 32];
        uint4* dstH = (uint4*)(g_khi + (size_t)uu * TT + t0 + half * 32);
        uint4* dstL = (uint4*)(g_klo + (size_t)uu * TT + t0 + half * 32);
        #pragma unroll
        for (int q = 0; q < 4; q++) { dstH[q] = srcH[q]; dstL[q] = srcL[q]; }
    }
}

// ============================================================
// Phase 2: per-player scan over 512 chunk-ops (+ zero g_y)
// ============================================================
__global__ void k_scan(const float* __restrict__ state) {
    int gtid = blockIdx.x * blockDim.x + threadIdx.x;
    ((float4*)g_y)[gtid] = make_float4(0.f, 0.f, 0.f, 0.f);

    int p    = gtid >> 5;
    int lane = gtid & 31;
    const int CPL = NC / 32;

    float L[CPL], H[CPL];
    int base = p * NC + lane * CPL;
    #pragma unroll
    for (int i = 0; i < CPL; i++) { L[i] = g_L[base + i]; H[i] = g_H[base + i]; }

    float l = L[0], h = H[0];
    #pragma unroll
    for (int i = 1; i < CPL; i++) combine(l, h, L[i], H[i]);

    #pragma unroll
    for (int d = 1; d < 32; d <<= 1) {
        float lo = __shfl_up_sync(0xffffffffu, l, d);
        float ho = __shfl_up_sync(0xffffffffu, h, d);
        if (lane >= d) {
            float nl = fminf(fmaxf(lo, l), h);
            float nh = fminf(fmaxf(ho, l), h);
            l = nl; h = nh;
        }
    }
    float exl = __shfl_up_sync(0xffffffffu, l, 1);
    float exh = __shfl_up_sync(0xffffffffu, h, 1);

    float s = state[p];
    if (lane > 0) s = fminf(fmaxf(s, exl), exh);
    #pragma unroll
    for (int i = 0; i < CPL; i++) {
        g_sin[base + i] = s;
        s = fminf(fmaxf(s, L[i]), H[i]);
    }
}

// ============================================================
// Phase 3: persistent HMMA GEMM with fused replay.
// Grid (74,2), 256 threads (8 warps). Warp tile: 32 players x 64 units.
// SMEM: A hi/lo [128p][136 bf16], B double-buffered hi/lo [128u][136 bf16].
// Accumulate in registers across ~7 chunks; one atomicAdd pass at end.
// ============================================================
#define ASTRIDE 272              // bytes per row (136 halves)
#define AHI_OFF 0
#define ALO_OFF 34816
#define B_OFF   69632
#define BBUF    69632            // per-buffer size (hi+lo)
#define SMEM_TOT (B_OFF + 2 * BBUF)

__global__ void __launch_bounds__(256, 1)
k_gemm(const float* __restrict__ x, const float* __restrict__ w) {
    extern __shared__ char smem[];
    const uint32_t sb = smem_u32(smem);
    const int tid  = threadIdx.x;
    const int warp = tid >> 5;
    const int lane = tid & 31;
    const int bx = blockIdx.x;           // 0..73
    const int p0 = blockIdx.y * 128;
    const int rg = warp >> 1;            // 0..3  player group (32)
    const int cg = warp & 1;             // 0..1  unit group (64)

    float acc[2][8][4];
    #pragma unroll
    for (int a = 0; a < 2; a++)
        #pragma unroll
        for (int b = 0; b < 8; b++)
            #pragma unroll
            for (int r = 0; r < 4; r++) acc[a][b][r] = 0.f;

    // B tile loader (cp.async): both hi & lo subtiles for chunk c -> buf
    auto loadB = [&](int c, int buf) {
        uint32_t dbase = sb + B_OFF + buf * BBUF;
        #pragma unroll
        for (int q = 0; q < 16; q++) {
            int idx = q * 256 + tid;         // 0..4095
            int type = idx >> 11;            // 0 hi, 1 lo
            int r = idx & 2047;
            int u = r >> 4, seg = r & 15;
            const __nv_bfloat16* src = type ? g_klo : g_khi;
            cp16(dbase + type * ALO_OFF + u * ASTRIDE + seg * 16,
                 (const char*)(src + (size_t)u * TT + (size_t)c * TC) + seg * 16);
        }
    };

    const int nchunks = (511 - bx) / 74 + 1;

    // ldmatrix lane base offsets
    const uint32_t aRowOff = (uint32_t)(rg * 32 + (lane & 15)) * ASTRIDE + (lane >> 4) * 16;
    const uint32_t bRowOff = (uint32_t)(cg * 64 + (lane & 7) + 8 * (lane >> 4)) * ASTRIDE
                           + ((lane >> 3) & 1) * 16;

    loadB(bx, 0);
    CP_COMMIT();

    for (int i = 0; i < nchunks; i++) {
        int c  = bx + i * 74;
        int tc = c * TC;

        // ---- replay scan: warp handles 16 players, 4 t per lane ----
        #pragma unroll 1
        for (int j = 0; j < 16; j++) {
            int pl = warp * 16 + j;
            float4 xv = __ldg((const float4*)(x + (size_t)(p0 + pl) * TT + tc) + lane);
            float wp   = __ldg(&w[p0 + pl]);
            float sin_ = __ldg(&g_sin[(size_t)(p0 + pl) * NC + c]);
            float x0 = xv.x * wp, x1 = xv.y * wp, x2 = xv.z * wp, x3 = xv.w * wp;

            float l = x0, h = x0 + 1.0f;
            combine(l, h, x1, x1 + 1.0f);
            combine(l, h, x2, x2 + 1.0f);
            combine(l, h, x3, x3 + 1.0f);
            #pragma unroll
            for (int d = 1; d < 32; d <<= 1) {
                float lo = __shfl_up_sync(0xffffffffu, l, d);
                float ho = __shfl_up_sync(0xffffffffu, h, d);
                if (lane >= d) {
                    float nl = fminf(fmaxf(lo, l), h);
                    float nh = fminf(fmaxf(ho, l), h);
                    l = nl; h = nh;
                }
            }
            float el = __shfl_up_sync(0xffffffffu, l, 1);
            float eh = __shfl_up_sync(0xffffffffu, h, 1);
            float s = sin_;
            if (lane) s = fminf(fmaxf(s, el), eh);

            float s0 = fminf(fmaxf(s,  x0), x0 + 1.0f);
            float s1 = fminf(fmaxf(s0, x1), x1 + 1.0f);
            float s2 = fminf(fmaxf(s1, x2), x2 + 1.0f);
            float s3 = fminf(fmaxf(s2, x3), x3 + 1.0f);

            uint32_t h0, h1;
            asm("cvt.rn.bf16x2.f32 %0, %1, %2;" : "=r"(h0) : "f"(s1), "f"(s0));
            asm("cvt.rn.bf16x2.f32 %0, %1, %2;" : "=r"(h1) : "f"(s3), "f"(s2));
            float r0 = s0 - __bfloat162float(__float2bfloat16(s0));
            float r1 = s1 - __bfloat162float(__float2bfloat16(s1));
            float r2 = s2 - __bfloat162float(__float2bfloat16(s2));
            float r3 = s3 - __bfloat162float(__float2bfloat16(s3));
            uint32_t l0, l1;
            asm("cvt.rn.bf16x2.f32 %0, %1, %2;" : "=r"(l0) : "f"(r1), "f"(r0));
            asm("cvt.rn.bf16x2.f32 %0, %1, %2;" : "=r"(l1) : "f"(r3), "f"(r2));

            uint32_t off = (uint32_t)pl * ASTRIDE + lane * 8;
            asm volatile("st.shared.v2.b32 [%0], {%1, %2};"
                         :: "r"(sb + AHI_OFF + off), "r"(h0), "r"(h1) : "memory");
            asm volatile("st.shared.v2.b32 [%0], {%1, %2};"
                         :: "r"(sb + ALO_OFF + off), "r"(l0), "r"(l1) : "memory");
        }

        CP_WAIT0();                       // B(c) resident
        __syncthreads();                  // A stores + B visible

        if (i + 1 < nchunks) { loadB(c + 74, (i + 1) & 1); CP_COMMIT(); }

        const uint32_t bbase = sb + B_OFF + (i & 1) * BBUF;

        #pragma unroll
        for (int ks = 0; ks < 8; ks++) {
            uint32_t kof = ks * 32;       // 16 halves = 32 bytes
            uint32_t ahi[2][4], alo[2][4];
            LDSM_X4(ahi[0], sb + AHI_OFF + aRowOff + kof);
            LDSM_X4(ahi[1], sb + AHI_OFF + aRowOff + 16 * ASTRIDE + kof);
            LDSM_X4(alo[0], sb + ALO_OFF + aRowOff + kof);
            LDSM_X4(alo[1], sb + ALO_OFF + aRowOff + 16 * ASTRIDE + kof);

            #pragma unroll
            for (int q = 0; q < 4; q++) {
                uint32_t bh[4], bl[4];
                LDSM_X4(bh, bbase + bRowOff + q * 16 * ASTRIDE + kof);
                LDSM_X4(bl, bbase + ALO_OFF + bRowOff + q * 16 * ASTRIDE + kof);
                #pragma unroll
                for (int t2 = 0; t2 < 2; t2++) {
                    int nt = 2 * q + t2;
                    MMA_BF16(acc[0][nt], ahi[0], bh[2*t2], bh[2*t2+1]);
                    MMA_BF16(acc[1][nt], ahi[1], bh[2*t2], bh[2*t2+1]);
                    MMA_BF16(acc[0][nt], alo[0], bh[2*t2], bh[2*t2+1]);
                    MMA_BF16(acc[1][nt], alo[1], bh[2*t2], bh[2*t2+1]);
                    MMA_BF16(acc[0][nt], ahi[0], bl[2*t2], bl[2*t2+1]);
                    MMA_BF16(acc[1][nt], ahi[1], bl[2*t2], bl[2*t2+1]);
                }
            }
        }
        __syncthreads();                  // A/B reuse guard
    }

    // ---- single atomic pass ----
    #pragma unroll
    for (int mt = 0; mt < 2; mt++) {
        #pragma unroll
        for (int nt = 0; nt < 8; nt++) {
            #pragma unroll
            for (int r = 0; r < 4; r++) {
                int row = p0 + rg * 32 + mt * 16 + (lane >> 2) + ((r >> 1) ? 8 : 0);
                int col = cg * 64 + nt * 8 + (lane & 3) * 2 + (r & 1);
                atomicAdd(&g_y[row * UU + col], acc[mt][nt][r]);
            }
        }
    }
}

// ============================================================
// Phase 4: epilogue  out = tanh(y + bias)
// ============================================================
__global__ void k_out(const float* __restrict__ bias, float* __restrict__ out) {
    int i = blockIdx.x * blockDim.x + threadIdx.x;
    out[i] = tanhf(g_y[i] + bias[i & (UU - 1)]);
}

// ============================================================
extern "C" void kernel_launch(void* const* d_in, const int* in_sizes, int n_in,
                              void* d_out, int out_size) {
    const float* inputs = (const float*)d_in[0];
    const float* pw     = (const float*)d_in[1];
    const float* kern   = (const float*)d_in[2];
    const float* bias   = (const float*)d_in[3];
    const float* state  = (const float*)d_in[4];
    float* out = (float*)d_out;

    cudaFuncSetAttribute(k_gemm, cudaFuncAttributeMaxDynamicSharedMemorySize, SMEM_TOT);

    k_phase1<<<(PP * NC) / 8 + TT / 64, 256>>>(inputs, pw, kern);
    k_scan<<<32, 256>>>(state);
    k_gemm<<<dim3(74, 2), 256, SMEM_TOT>>>(inputs, pw);
    k_out<<<(PP * UU) / 256, 256>>>(bias, out);
}

// round 4
// speedup vs baseline: 2.1757x; 1.3961x over previous
#include <cuda_runtime.h>
#include <cuda_bf16.h>
#include <math.h>
#include <stdint.h>

#define PP 256
#define TT 65536
#define UU 128
#define TC 128            // GEMM chunk (t)
#define NC 512            // GEMM chunks
#define NCS 1024          // scan chunks (64 t each)

// ---------------- device scratch ----------------
__device__ __align__(16) float g_L[PP*NCS];
__device__ __align__(16) float g_H[PP*NCS];
__device__ __align__(16) float g_sin[PP*NCS];
__device__ __align__(16) float g_y[PP*UU];
__device__ __align__(16) __nv_bfloat16 g_khi[(size_t)UU*TT];   // [U][T]
__device__ __align__(16) __nv_bfloat16 g_klo[(size_t)UU*TT];   // [U][T]

// ---------------- helpers ----------------
__device__ __forceinline__ uint32_t smem_u32(const void* p) {
    uint32_t a;
    asm("{ .reg .u64 t; cvta.to.shared.u64 t, %1; cvt.u32.u64 %0, t; }" : "=r"(a) : "l"(p));
    return a;
}
__device__ __forceinline__ void cp16(uint32_t dst, const void* src) {
    asm volatile("cp.async.cg.shared.global [%0], [%1], 16;" :: "r"(dst), "l"(src));
}
#define CP_COMMIT() asm volatile("cp.async.commit_group;" ::: "memory")
#define CP_WAIT0()  asm volatile("cp.async.wait_group 0;" ::: "memory")

#define LDSM_X4(d, addr) \
    asm volatile("ldmatrix.sync.aligned.m8n8.x4.shared.b16 {%0,%1,%2,%3}, [%4];" \
        : "=r"((d)[0]), "=r"((d)[1]), "=r"((d)[2]), "=r"((d)[3]) : "r"(addr))

#define MMA_BF16(c, a, b0, b1) \
    asm volatile("mma.sync.aligned.m16n8k16.row.col.f32.bf16.bf16.f32 " \
        "{%0,%1,%2,%3}, {%4,%5,%6,%7}, {%8,%9}, {%0,%1,%2,%3};" \
        : "+f"((c)[0]), "+f"((c)[1]), "+f"((c)[2]), "+f"((c)[3]) \
        : "r"((a)[0]), "r"((a)[1]), "r"((a)[2]), "r"((a)[3]), "r"(b0), "r"(b1))

__device__ __forceinline__ void combine(float& l, float& h, float l2, float h2) {
    l = fminf(fmaxf(l, l2), h2);
    h = fminf(fmaxf(h, l2), h2);
}

// ============================================================
// Phase 1 (fused): 64-t chunk reductions + kernel transpose/split
// ============================================================
__global__ void k_phase1(const float* __restrict__ x, const float* __restrict__ w,
                         const float* __restrict__ kern) {
    if (blockIdx.x < (PP * NC) / 8) {
        // one warp per 128-t span; produces TWO 64-t chunk (L,H) pairs
        int wid  = (blockIdx.x * blockDim.x + threadIdx.x) >> 5;
        int lane = threadIdx.x & 31;
        int p = wid >> 9;            // / 512
        int c = wid & (NC - 1);      // 128-t span

        float wp = __ldg(&w[p]);
        const float4 xv = *(const float4*)(x + (size_t)p * TT + (size_t)c * TC + lane * 4);
        float x0 = xv.x * wp, x1 = xv.y * wp, x2 = xv.z * wp, x3 = xv.w * wp;

        float l = x0, h = x0 + 1.0f;
        combine(l, h, x1, x1 + 1.0f);
        combine(l, h, x2, x2 + 1.0f);
        combine(l, h, x3, x3 + 1.0f);
        // reduce within each 16-lane half (64 t each)
        #pragma unroll
        for (int d = 1; d < 16; d <<= 1) {
            float lo = __shfl_down_sync(0xffffffffu, l, d);
            float ho = __shfl_down_sync(0xffffffffu, h, d);
            if ((lane & 15) + d < 16) combine(l, h, lo, ho);
        }
        if ((lane & 15) == 0) {
            int c2 = c * 2 + (lane >> 4);
            g_L[p * NCS + c2] = l;
            g_H[p * NCS + c2] = h;
        }
    } else {
        // transpose + bf16 hi/lo split of kernel: 64-t tile
        __shared__ __nv_bfloat16 sh[128][72];
        __shared__ __nv_bfloat16 sl[128][72];
        int tb = blockIdx.x - (PP * NC) / 8;
        int t0 = tb * 64;
        int u = threadIdx.x & 127, rh = threadIdx.x >> 7;
        #pragma unroll 8
        for (int rr = 0; rr < 64; rr += 2) {
            int t = t0 + rr + rh;
            float v = __ldg(&kern[(size_t)t * UU + u]);
            __nv_bfloat16 hi = __float2bfloat16(v);
            float lo = v - __bfloat162float(hi);
            sh[u][rr + rh] = hi;
            sl[u][rr + rh] = __float2bfloat16(lo);
        }
        __syncthreads();
        int uu = threadIdx.x >> 1, half = threadIdx.x & 1;
        const uint4* srcH = (const uint4*)&sh[uu][half * 32];
        const uint4* srcL = (const uint4*)&sl[uu][half * 32];
        uint4* dstH = (uint4*)(g_khi + (size_t)uu * TT + t0 + half * 32);
        uint4* dstL = (uint4*)(g_klo + (size_t)uu * TT + t0 + half * 32);
        #pragma unroll
        for (int q = 0; q < 4; q++) { dstH[q] = srcH[q]; dstL[q] = srcL[q]; }
    }
}

// ============================================================
// Phase 2: per-player scan over 1024 chunk-ops (+ zero g_y)
// ============================================================
__global__ void k_scan(const float* __restrict__ state) {
    int gtid = blockIdx.x * blockDim.x + threadIdx.x;   // 0..8191
    ((float4*)g_y)[gtid] = make_float4(0.f, 0.f, 0.f, 0.f);

    int p    = gtid >> 5;
    int lane = gtid & 31;
    const int CPL = NCS / 32;   // 32

    float L[CPL], H[CPL];
    int base = p * NCS + lane * CPL;
    #pragma unroll
    for (int i = 0; i < CPL; i++) { L[i] = g_L[base + i]; H[i] = g_H[base + i]; }

    float l = L[0], h = H[0];
    #pragma unroll
    for (int i = 1; i < CPL; i++) combine(l, h, L[i], H[i]);

    #pragma unroll
    for (int d = 1; d < 32; d <<= 1) {
        float lo = __shfl_up_sync(0xffffffffu, l, d);
        float ho = __shfl_up_sync(0xffffffffu, h, d);
        if (lane >= d) {
            float nl = fminf(fmaxf(lo, l), h);
            float nh = fminf(fmaxf(ho, l), h);
            l = nl; h = nh;
        }
    }
    float exl = __shfl_up_sync(0xffffffffu, l, 1);
    float exh = __shfl_up_sync(0xffffffffu, h, 1);

    float s = state[p];
    if (lane > 0) s = fminf(fmaxf(s, exl), exh);
    #pragma unroll
    for (int i = 0; i < CPL; i++) {
        g_sin[base + i] = s;
        s = fminf(fmaxf(s, L[i]), H[i]);
    }
}

// ============================================================
// Phase 3: persistent HMMA GEMM with fused lane-serial replay.
// Grid (74,2), 8 warps. Warp (sub=w>>2, pg=w&3): lane owns player
// pg*32+lane, scans t-half sub (64 steps, registers only, no shfl).
// ============================================================
#define ASTRIDE 272              // bytes per A/B row (136 halves)
#define AHI_OFF 0
#define ALO_OFF 34816
#define B_OFF   69632
#define BBUF    69632
#define SMEM_TOT (B_OFF + 2 * BBUF)

__global__ void __launch_bounds__(256, 1)
k_gemm(const float* __restrict__ x, const float* __restrict__ w) {
    extern __shared__ char smem[];
    const uint32_t sb = smem_u32(smem);
    const int tid  = threadIdx.x;
    const int warp = tid >> 5;
    const int lane = tid & 31;
    const int bx = blockIdx.x;           // 0..73
    const int p0 = blockIdx.y * 128;
    const int rg = warp >> 1;            // MMA: player group (32)
    const int cg = warp & 1;             // MMA: unit group (64)
    const int sub = warp >> 2;           // scan: t-half (0/1)
    const int pg  = warp & 3;            // scan: player group (32)

    float acc[2][8][4];
    #pragma unroll
    for (int a = 0; a < 2; a++)
        #pragma unroll
        for (int b = 0; b < 8; b++)
            #pragma unroll
            for (int r = 0; r < 4; r++) acc[a][b][r] = 0.f;

    auto loadB = [&](int c, int buf) {
        uint32_t dbase = sb + B_OFF + buf * BBUF;
        #pragma unroll
        for (int q = 0; q < 16; q++) {
            int idx = q * 256 + tid;
            int type = idx >> 11;
            int r = idx & 2047;
            int u = r >> 4, seg = r & 15;
            const __nv_bfloat16* src = type ? g_klo : g_khi;
            cp16(dbase + type * ALO_OFF + u * ASTRIDE + seg * 16,
                 (const char*)(src + (size_t)u * TT + (size_t)c * TC) + seg * 16);
        }
    };

    const int nchunks = (511 - bx) / 74 + 1;

    const uint32_t aRowOff = (uint32_t)(rg * 32 + (lane & 15)) * ASTRIDE + (lane >> 4) * 16;
    const uint32_t bRowOff = (uint32_t)(cg * 64 + (lane & 7) + 8 * (lane >> 4)) * ASTRIDE
                           + ((lane >> 3) & 1) * 16;

    // scan-side per-lane constants
    const int pl = pg * 32 + lane;               // player row within tile
    const int p  = p0 + pl;
    const float wp = __ldg(&w[p]);
    const uint32_t arowH = sb + AHI_OFF + (uint32_t)pl * ASTRIDE + sub * 128;
    const uint32_t arowL = sb + ALO_OFF + (uint32_t)pl * ASTRIDE + sub * 128;

    loadB(bx, 0);
    CP_COMMIT();

    for (int i = 0; i < nchunks; i++) {
        int c  = bx + i * 74;
        int tc = c * TC;

        CP_WAIT0();              // B_i resident
        __syncthreads();         // + prev MMA done reading A

        if (i + 1 < nchunks) { loadB(c + 74, (i + 1) & 1); CP_COMMIT(); }

        // ---- lane-serial replay: 64 clamp steps, registers only ----
        {
            float s = __ldg(&g_sin[(size_t)p * NCS + c * 2 + sub]);
            const float4* xr = (const float4*)(x + (size_t)p * TT + tc + sub * 64);
            #pragma unroll
            for (int g = 0; g < 4; g++) {
                float4 v0 = __ldg(xr + g * 4 + 0);
                float4 v1 = __ldg(xr + g * 4 + 1);
                float4 v2 = __ldg(xr + g * 4 + 2);
                float4 v3 = __ldg(xr + g * 4 + 3);
                float xs[16] = { v0.x*wp, v0.y*wp, v0.z*wp, v0.w*wp,
                                 v1.x*wp, v1.y*wp, v1.z*wp, v1.w*wp,
                                 v2.x*wp, v2.y*wp, v2.z*wp, v2.w*wp,
                                 v3.x*wp, v3.y*wp, v3.z*wp, v3.w*wp };
                float ss[16];
                #pragma unroll
                for (int t2 = 0; t2 < 16; t2++) {
                    s = fminf(fmaxf(s, xs[t2]), xs[t2] + 1.0f);
                    ss[t2] = s;
                }
                uint32_t hw[8], lw[8];
                #pragma unroll
                for (int j = 0; j < 8; j++) {
                    float a0 = ss[2*j], a1 = ss[2*j+1];
                    asm("cvt.rn.bf16x2.f32 %0, %1, %2;" : "=r"(hw[j]) : "f"(a1), "f"(a0));
                    float r0 = a0 - __bfloat162float(__float2bfloat16(a0));
                    float r1 = a1 - __bfloat162float(__float2bfloat16(a1));
                    asm("cvt.rn.bf16x2.f32 %0, %1, %2;" : "=r"(lw[j]) : "f"(r1), "f"(r0));
                }
                asm volatile("st.shared.v4.b32 [%0], {%1,%2,%3,%4};"
                    :: "r"(arowH + g*32), "r"(hw[0]), "r"(hw[1]), "r"(hw[2]), "r"(hw[3]) : "memory");
                asm volatile("st.shared.v4.b32 [%0], {%1,%2,%3,%4};"
                    :: "r"(arowH + g*32 + 16), "r"(hw[4]), "r"(hw[5]), "r"(hw[6]), "r"(hw[7]) : "memory");
                asm volatile("st.shared.v4.b32 [%0], {%1,%2,%3,%4};"
                    :: "r"(arowL + g*32), "r"(lw[0]), "r"(lw[1]), "r"(lw[2]), "r"(lw[3]) : "memory");
                asm volatile("st.shared.v4.b32 [%0], {%1,%2,%3,%4};"
                    :: "r"(arowL + g*32 + 16), "r"(lw[4]), "r"(lw[5]), "r"(lw[6]), "r"(lw[7]) : "memory");
            }
        }
        __syncthreads();

        const uint32_t bbase = sb + B_OFF + (i & 1) * BBUF;

        #pragma unroll
        for (int ks = 0; ks < 8; ks++) {
            uint32_t kof = ks * 32;
            uint32_t ahi[2][4], alo[2][4];
            LDSM_X4(ahi[0], sb + AHI_OFF + aRowOff + kof);
            LDSM_X4(ahi[1], sb + AHI_OFF + aRowOff + 16 * ASTRIDE + kof);
            LDSM_X4(alo[0], sb + ALO_OFF + aRowOff + kof);
            LDSM_X4(alo[1], sb + ALO_OFF + aRowOff + 16 * ASTRIDE + kof);

            #pragma unroll
            for (int q = 0; q < 4; q++) {
                uint32_t bh[4], bl[4];
                LDSM_X4(bh, bbase + bRowOff + q * 16 * ASTRIDE + kof);
                LDSM_X4(bl, bbase + ALO_OFF + bRowOff + q * 16 * ASTRIDE + kof);
                #pragma unroll
                for (int t2 = 0; t2 < 2; t2++) {
                    int nt = 2 * q + t2;
                    MMA_BF16(acc[0][nt], ahi[0], bh[2*t2], bh[2*t2+1]);
                    MMA_BF16(acc[1][nt], ahi[1], bh[2*t2], bh[2*t2+1]);
                    MMA_BF16(acc[0][nt], alo[0], bh[2*t2], bh[2*t2+1]);
                    MMA_BF16(acc[1][nt], alo[1], bh[2*t2], bh[2*t2+1]);
                    MMA_BF16(acc[0][nt], ahi[0], bl[2*t2], bl[2*t2+1]);
                    MMA_BF16(acc[1][nt], ahi[1], bl[2*t2], bl[2*t2+1]);
                }
            }
        }
    }

    // ---- single atomic pass ----
    #pragma unroll
    for (int mt = 0; mt < 2; mt++) {
        #pragma unroll
        for (int nt = 0; nt < 8; nt++) {
            #pragma unroll
            for (int r = 0; r < 4; r++) {
                int row = p0 + rg * 32 + mt * 16 + (lane >> 2) + ((r >> 1) ? 8 : 0);
                int col = cg * 64 + nt * 8 + (lane & 3) * 2 + (r & 1);
                atomicAdd(&g_y[row * UU + col], acc[mt][nt][r]);
            }
        }
    }
}

// ============================================================
// Phase 4: epilogue  out = tanh(y + bias)   (vectorized)
// ============================================================
__global__ void k_out(const float* __restrict__ bias, float* __restrict__ out) {
    int i = blockIdx.x * blockDim.x + threadIdx.x;   // 0..8191
    float4 v = ((const float4*)g_y)[i];
    float4 b = ((const float4*)bias)[i & 31];
    float4 o;
    o.x = tanhf(v.x + b.x); o.y = tanhf(v.y + b.y);
    o.z = tanhf(v.z + b.z); o.w = tanhf(v.w + b.w);
    ((float4*)out)[i] = o;
}

// ============================================================
extern "C" void kernel_launch(void* const* d_in, const int* in_sizes, int n_in,
                              void* d_out, int out_size) {
    const float* inputs = (const float*)d_in[0];
    const float* pw     = (const float*)d_in[1];
    const float* kern   = (const float*)d_in[2];
    const float* bias   = (const float*)d_in[3];
    const float* state  = (const float*)d_in[4];
    float* out = (float*)d_out;

    cudaFuncSetAttribute(k_gemm, cudaFuncAttributeMaxDynamicSharedMemorySize, SMEM_TOT);

    k_phase1<<<(PP * NC) / 8 + TT / 64, 256>>>(inputs, pw, kern);
    k_scan<<<32, 256>>>(state);
    k_gemm<<<dim3(74, 2), 256, SMEM_TOT>>>(inputs, pw);
    k_out<<<32, 256>>>(bias, out);
}